// round 13
// baseline (speedup 1.0000x reference)
#include <cuda_runtime.h>
#include <cuda_fp16.h>
#include <math.h>
#include <stdint.h>

// Problem dims (fixed by the reference)
#define Bsz 2
#define Ssz 2048
#define Esz 1024
#define Hsz 16
#define Dsz 64
#define FFsz 4096
#define Msz (Bsz*Ssz)   // 4096 tokens

// ===================== helpers ===============================================
__device__ __forceinline__ uint32_t smem_to_u32(const void* p) {
    uint32_t a;
    asm("{ .reg .u64 t; cvta.to.shared.u64 t, %1; cvt.u32.u64 %0, t; }" : "=r"(a) : "l"(p));
    return a;
}
#define CPASYNC16(saddr, gptr) \
    asm volatile("cp.async.cg.shared.global [%0], [%1], 16;" :: "r"((uint32_t)(saddr)), "l"(gptr))
#define CPASYNC_COMMIT() asm volatile("cp.async.commit_group;" ::: "memory")
#define CPASYNC_WAIT2() asm volatile("cp.async.wait_group 2;" ::: "memory")
#define CPASYNC_WAIT1() asm volatile("cp.async.wait_group 1;" ::: "memory")
#define CPASYNC_WAIT0() asm volatile("cp.async.wait_group 0;" ::: "memory")

__device__ __forceinline__ void ldmatrix_x4(uint32_t& r0, uint32_t& r1, uint32_t& r2, uint32_t& r3,
                                            uint32_t addr) {
    asm volatile("ldmatrix.sync.aligned.m8n8.x4.shared.b16 {%0,%1,%2,%3}, [%4];"
        : "=r"(r0), "=r"(r1), "=r"(r2), "=r"(r3) : "r"(addr));
}
__device__ __forceinline__ void ldmatrix_x4_trans(uint32_t& r0, uint32_t& r1, uint32_t& r2, uint32_t& r3,
                                                  uint32_t addr) {
    asm volatile("ldmatrix.sync.aligned.m8n8.x4.trans.shared.b16 {%0,%1,%2,%3}, [%4];"
        : "=r"(r0), "=r"(r1), "=r"(r2), "=r"(r3) : "r"(addr));
}
__device__ __forceinline__ void mma16816(float* d, const uint32_t* a, const uint32_t* b) {
    asm volatile("mma.sync.aligned.m16n8k16.row.col.f32.f16.f16.f32 "
        "{%0,%1,%2,%3}, {%4,%5,%6,%7}, {%8,%9}, {%0,%1,%2,%3};"
        : "+f"(d[0]), "+f"(d[1]), "+f"(d[2]), "+f"(d[3])
        : "r"(a[0]), "r"(a[1]), "r"(a[2]), "r"(a[3]), "r"(b[0]), "r"(b[1]));
}
// swizzled address: row-major, row bytes rb (multiple of 128), XOR within 128B blocks
__device__ __forceinline__ uint32_t swadr(uint32_t row, uint32_t rb, uint32_t c) {
    return row * rb + (c & ~127u) + ((c & 127u) ^ ((row & 7u) * 16u));
}

// ===================== side stream (created at static init, host objects) ====
struct SideCtx {
    cudaStream_t s;
    cudaEvent_t fork, join;
    SideCtx() {
        cudaStreamCreateWithFlags(&s, cudaStreamNonBlocking);
        cudaEventCreateWithFlags(&fork, cudaEventDisableTiming);
        cudaEventCreateWithFlags(&join, cudaEventDisableTiming);
    }
};
static SideCtx g_side;

// ===================== scratch (device globals) ==============================
__device__ __half g_proj16[(size_t)Msz * Esz];
__device__ __half g_ff16[(size_t)Msz * Esz];
__device__ __half g_q2[(size_t)Msz * Esz];            // [tok][h][d]
__device__ __half g_k2[(size_t)Msz * Esz];            // [tok][h][d]
__device__ __half g_v2[(size_t)Msz * Esz];            // [tok][h][d]  (natural)
__device__ __half g_attn2[(size_t)Msz * Esz];
__device__ __half g_x2[(size_t)Msz * Esz];
__device__ __half g_x12[(size_t)Msz * Esz];
__device__ __half g_h2[(size_t)Msz * FFsz];
__device__ __half g_wqkv2[(size_t)(3 * Esz) * Esz];
__device__ __half g_wout2[(size_t)Esz * Esz];
__device__ __half g_wfc12[(size_t)FFsz * Esz];
__device__ __half g_wfc22[(size_t)Esz * FFsz];

// ===================== fp32->fp16 converts ===================================
// 8 elements per thread-iter: 2x float4 loads -> one 16B store.
__device__ __forceinline__ void cvt_seg(const float* __restrict__ s, __half* __restrict__ d,
                                        int n8, int base, int stride)
{
    for (int i = base; i < n8; i += stride) {
        const float4 f0 = ((const float4*)s)[2 * i];
        const float4 f1 = ((const float4*)s)[2 * i + 1];
        const __half2 h0 = __floats2half2_rn(f0.x, f0.y);
        const __half2 h1 = __floats2half2_rn(f0.z, f0.w);
        const __half2 h2 = __floats2half2_rn(f1.x, f1.y);
        const __half2 h3 = __floats2half2_rn(f1.z, f1.w);
        uint4 o;
        o.x = *(const uint32_t*)&h0;
        o.y = *(const uint32_t*)&h1;
        o.z = *(const uint32_t*)&h2;
        o.w = *(const uint32_t*)&h3;
        ((uint4*)d)[i] = o;
    }
}
// critical path: w_qkv + x (needed by the first GEMM)
__global__ __launch_bounds__(256)
void cvt_crit_kernel(const float* w_qkv, const float* x, __half* wq2, __half* x2)
{
    const int base = blockIdx.x * 256 + threadIdx.x;
    const int stride = gridDim.x * 256;
    cvt_seg(w_qkv, wq2, (3 * Esz * Esz) / 8, base, stride);
    cvt_seg(x, x2, (Msz * Esz) / 8, base, stride);
}
// non-critical: w_out/w_fc1/w_fc2 (overlapped on side stream)
__global__ __launch_bounds__(256)
void cvt_rest_kernel(const float* w_out, const float* w_fc1, const float* w_fc2,
                     __half* wo2, __half* w12, __half* w22)
{
    const int base = blockIdx.x * 256 + threadIdx.x;
    const int stride = gridDim.x * 256;
    cvt_seg(w_out, wo2, (Esz * Esz) / 8, base, stride);
    cvt_seg(w_fc1, w12, (FFsz * Esz) / 8, base, stride);
    cvt_seg(w_fc2, w22, (Esz * FFsz) / 8, base, stride);
}

// ===================== HMMA fp16 GEMM (128x128 tile, 128 thr, 64x64 warp) ====
// C = A*B^T + bias. MODE 1: qkv split (q/k/v natural fp16).
// MODE 2: GELU + fp16 out. MODE 3: fp16 out (no act).
#define NBUF 3
#define STAGE_BYTES (128 * 128)
#define STAGE_AB (2 * STAGE_BYTES)
#define GEMM_SMEM (NBUF * STAGE_AB)

template<int MODE>
__global__ __launch_bounds__(128, 2)
void gemm_mma_kernel(const __half* __restrict__ A, const __half* __restrict__ Bm,
                     const float* __restrict__ bias,
                     __half* __restrict__ C3,
                     __half* __restrict__ q2p, __half* __restrict__ k2p, __half* __restrict__ v2p,
                     int N, int K2, int lda, int ldb)
{
    extern __shared__ __align__(1024) char smem[];
    const uint32_t sbase = smem_to_u32(smem);
    const int tid = threadIdx.x;
    const int lane = tid & 31;
    const int wid = tid >> 5;
    const int wm = wid & 1;        // 2 m-warps (64 rows each)
    const int wn = wid >> 1;       // 2 n-warps (64 cols each)
    const int bx = blockIdx.x, by = blockIdx.y;

    // fill: 8 x 16B chunks per thread per operand per stage (128 threads)
    uint32_t st_off[8];
    const char* Agp[8];
    const char* Bgp[8];
    #pragma unroll
    for (int t = 0; t < 8; t++) {
        const int idx = tid + t * 128;
        const int row = idx >> 3, c = (idx & 7) * 16;
        st_off[t] = (uint32_t)(row * 128 + (c ^ ((row & 7) * 16)));
        Agp[t] = (const char*)A + ((size_t)(by * 128 + row) * lda + (idx & 7) * 8) * 2;
        Bgp[t] = (const char*)Bm + ((size_t)(bx * 128 + row) * ldb + (idx & 7) * 8) * 2;
    }

    const uint32_t colxor = (uint32_t)((lane & 7) * 16);
    const uint32_t a_rowbase = (uint32_t)((wm * 64 + (lane & 15)) * 128);
    const uint32_t a_part = (uint32_t)((lane >> 4) * 16);
    const uint32_t b_rowbase = (uint32_t)((wn * 64 + ((lane >> 4) << 3) + (lane & 7)) * 128);
    const uint32_t b_part = (uint32_t)(((lane >> 3) & 1) * 16);

    float acc[4][8][4];
    #pragma unroll
    for (int i = 0; i < 4; i++)
        #pragma unroll
        for (int j = 0; j < 8; j++)
            #pragma unroll
            for (int u = 0; u < 4; u++) acc[i][j][u] = 0.0f;

    const int S = K2 / 64;

    #pragma unroll
    for (int p = 0; p < NBUF; p++) {
        const uint32_t ab = sbase + p * STAGE_AB;
        const uint32_t bb = ab + STAGE_BYTES;
        #pragma unroll
        for (int t = 0; t < 8; t++) {
            CPASYNC16(ab + st_off[t], Agp[t] + (size_t)p * 128);
            CPASYNC16(bb + st_off[t], Bgp[t] + (size_t)p * 128);
        }
        CPASYNC_COMMIT();
    }

    #pragma unroll 1
    for (int s = 0; s < S; s++) {
        if (s + NBUF <= S) CPASYNC_WAIT2();
        else               CPASYNC_WAIT0();
        __syncthreads();
        const uint32_t ab = sbase + (s % NBUF) * STAGE_AB;
        const uint32_t bb = ab + STAGE_BYTES;

        #pragma unroll
        for (int k = 0; k < 4; k++) {
            const uint32_t kb = (uint32_t)(k * 32);
            uint32_t a[4][4], b[8][2];
            #pragma unroll
            for (int i = 0; i < 4; i++)
                ldmatrix_x4(a[i][0], a[i][1], a[i][2], a[i][3],
                            ab + a_rowbase + (uint32_t)(i * 2048) + ((kb + a_part) ^ colxor));
            #pragma unroll
            for (int jp = 0; jp < 4; jp++) {
                uint32_t r0, r1, r2, r3;
                ldmatrix_x4(r0, r1, r2, r3,
                            bb + b_rowbase + (uint32_t)(jp * 2048) + ((kb + b_part) ^ colxor));
                b[2 * jp][0] = r0; b[2 * jp][1] = r1;
                b[2 * jp + 1][0] = r2; b[2 * jp + 1][1] = r3;
            }
            #pragma unroll
            for (int i = 0; i < 4; i++)
                #pragma unroll
                for (int j = 0; j < 8; j++)
                    mma16816(acc[i][j], a[i], b[j]);
        }
        __syncthreads();
        if (s + NBUF < S) {
            const int sn = s + NBUF;
            #pragma unroll
            for (int t = 0; t < 8; t++) {
                CPASYNC16(ab + st_off[t], Agp[t] + (size_t)sn * 128);
                CPASYNC16(bb + st_off[t], Bgp[t] + (size_t)sn * 128);
            }
            CPASYNC_COMMIT();
        }
    }

    // ---- epilogue ----
    const int row0 = by * 128 + wm * 64 + (lane >> 2);
    const int col0 = bx * 128 + wn * 64 + (lane & 3) * 2;
    #pragma unroll
    for (int j = 0; j < 8; j++) {
        const int col = col0 + j * 8;
        const float2 bv = *(const float2*)&bias[col];
        #pragma unroll
        for (int i = 0; i < 4; i++) {
            #pragma unroll
            for (int half = 0; half < 2; half++) {
                const int row = row0 + i * 16 + half * 8;
                float v0 = acc[i][j][half * 2 + 0] + bv.x;
                float v1 = acc[i][j][half * 2 + 1] + bv.y;
                if (MODE == 2) {
                    v0 = 0.5f * v0 * (1.0f + erff(v0 * 0.70710678118654752f));
                    v1 = 0.5f * v1 * (1.0f + erff(v1 * 0.70710678118654752f));
                    *(__half2*)(C3 + (size_t)row * N + col) =
                        __halves2half2(__float2half_rn(v0), __float2half_rn(v1));
                } else if (MODE == 3) {
                    *(__half2*)(C3 + (size_t)row * N + col) =
                        __halves2half2(__float2half_rn(v0), __float2half_rn(v1));
                } else {  // MODE 1: qkv split epilogue (all natural layouts)
                    const int sec = col >> 10;
                    const int within = col & 1023;
                    const __half2 hv = __halves2half2(__float2half_rn(v0), __float2half_rn(v1));
                    if (sec == 0)      *(__half2*)(q2p + (size_t)row * 1024 + within) = hv;
                    else if (sec == 1) *(__half2*)(k2p + (size_t)row * 1024 + within) = hv;
                    else               *(__half2*)(v2p + (size_t)row * 1024 + within) = hv;
                }
            }
        }
    }
}

// ===================== FA2 flash attention ===================================
// grid (S/128, H, B), 256 threads (8 warps, each owns 16 rows x full 64 n).
// Register softmax via h2exp2 (fp16 P is both PV A-operand and sum source).
// V natural [tok][d]; PV B-fragments via ldmatrix.trans. Triple-buffered K/V.
#define SQ2 0                    // 16KB (128 rows x 128B)
#define SKV 16384                // 3 x (8KB K + 8KB V)
#define AT_SMEM (16384 + 3 * 16384)

__global__ __launch_bounds__(256, 2)
void flash_mma_kernel(const __half* __restrict__ q2, const __half* __restrict__ k2,
                      const __half* __restrict__ v2, __half* __restrict__ attn2)
{
    extern __shared__ __align__(1024) char sm_[];
    const uint32_t sb = smem_to_u32(sm_);

    const int tid = threadIdx.x, lane = tid & 31, w = tid >> 5;
    const int qb = blockIdx.x, h = blockIdx.y, b = blockIdx.z;
    const int NKB = Ssz / 64;   // 32

    const char* qsrc = (const char*)q2 + ((size_t)(b * Ssz + qb * 128) * 1024 + h * 64) * 2;
    const char* ksrc = (const char*)k2 + ((size_t)b * Ssz * 1024 + h * 64) * 2;
    const char* vsrc = (const char*)v2 + ((size_t)b * Ssz * 1024 + h * 64) * 2;

    // ---- prologue: Q + (K,V)(0) [group0], (K,V)(1) [group1] ----
    #pragma unroll
    for (int it = 0; it < 4; it++) {
        const int idx = tid + it * 256;
        const int r = idx >> 3;
        const int c = (idx & 7) * 16;
        CPASYNC16(sb + SQ2 + swadr(r, 128, c), qsrc + (size_t)r * 2048 + c);
    }
    #pragma unroll
    for (int p = 0; p < 2; p++) {
        const uint32_t ko = SKV + p * 16384;
        const uint32_t vo = ko + 8192;
        #pragma unroll
        for (int it = 0; it < 2; it++) {
            const int idx = tid + it * 256;
            const int r = idx >> 3;
            const int c = (idx & 7) * 16;
            CPASYNC16(sb + ko + swadr(r, 128, c), ksrc + (size_t)(p * 64 + r) * 2048 + c);
            CPASYNC16(sb + vo + swadr(r, 128, c), vsrc + (size_t)(p * 64 + r) * 2048 + c);
        }
        CPASYNC_COMMIT();
    }

    const int a_row = lane & 15;
    const int a_part = (lane >> 4) * 16;
    const int b_rowo = ((lane >> 4) << 3) + (lane & 7);
    const int b_part = ((lane >> 3) & 1) * 16;
    // trans-ldmatrix lane map (B from token-major V tile)
    const int v_row = lane & 15;
    const int v_col = (lane >> 4) * 16;

    uint32_t q[4][4];
    float o[8][4];
    #pragma unroll
    for (int j = 0; j < 8; j++)
        #pragma unroll
        for (int u = 0; u < 4; u++) o[j][u] = 0.0f;
    float m0 = -INFINITY, m1 = -INFINITY, l0 = 0.0f, l1 = 0.0f;

    #pragma unroll 1
    for (int kb = 0; kb < NKB; kb++) {
        if (kb + 1 < NKB) CPASYNC_WAIT1();
        else              CPASYNC_WAIT0();
        __syncthreads();   // (a) K/V(kb) visible; (b) all warps past kb-1 reads

        // prefetch (kb+2) into buffer (kb+2)%3 — last read at iter kb-1
        if (kb + 2 < NKB) {
            const uint32_t ko = SKV + ((kb + 2) % 3) * 16384;
            const uint32_t vo = ko + 8192;
            #pragma unroll
            for (int it = 0; it < 2; it++) {
                const int idx = tid + it * 256;
                const int r = idx >> 3;
                const int c = (idx & 7) * 16;
                CPASYNC16(sb + ko + swadr(r, 128, c),
                          ksrc + (size_t)((kb + 2) * 64 + r) * 2048 + c);
                CPASYNC16(sb + vo + swadr(r, 128, c),
                          vsrc + (size_t)((kb + 2) * 64 + r) * 2048 + c);
            }
            CPASYNC_COMMIT();
        }

        if (kb == 0) {
            // load Q fragments once; pre-scale by 1/8 (exact in fp16)
            const __half2 sc = __half2half2(__float2half(0.125f));
            #pragma unroll
            for (int ks = 0; ks < 4; ks++) {
                ldmatrix_x4(q[ks][0], q[ks][1], q[ks][2], q[ks][3],
                            sb + SQ2 + swadr((uint32_t)(16 * w + a_row), 128,
                                             (uint32_t)(ks * 32 + a_part)));
                #pragma unroll
                for (int u = 0; u < 4; u++) {
                    __half2 t = *(__half2*)&q[ks][u];
                    t = __hmul2(t, sc);
                    q[ks][u] = *(uint32_t*)&t;
                }
            }
        }

        const uint32_t kbuf = sb + SKV + (kb % 3) * 16384;
        const uint32_t vbuf = kbuf + 8192;

        // ---- S = Q K^T : warp tile 16(m) x 64(n tokens), 4 k-steps ----
        float s[8][4];
        #pragma unroll
        for (int j = 0; j < 8; j++)
            #pragma unroll
            for (int u = 0; u < 4; u++) s[j][u] = 0.0f;

        #pragma unroll
        for (int ks = 0; ks < 4; ks++) {
            #pragma unroll
            for (int jb = 0; jb < 4; jb++) {
                uint32_t r0, r1, r2, r3;
                ldmatrix_x4(r0, r1, r2, r3,
                            kbuf + swadr((uint32_t)(jb * 16 + b_rowo), 128,
                                         (uint32_t)(ks * 32 + b_part)));
                uint32_t bfr0[2] = {r0, r1}, bfr1[2] = {r2, r3};
                mma16816(s[2 * jb], q[ks], bfr0);
                mma16816(s[2 * jb + 1], q[ks], bfr1);
            }
        }

        // ---- register online softmax (rows r0 = lane>>2, r1 = r0+8) ----
        float vmax0 = -INFINITY, vmax1 = -INFINITY;
        #pragma unroll
        for (int j = 0; j < 8; j++) {
            vmax0 = fmaxf(vmax0, fmaxf(s[j][0], s[j][1]));
            vmax1 = fmaxf(vmax1, fmaxf(s[j][2], s[j][3]));
        }
        vmax0 = fmaxf(vmax0, __shfl_xor_sync(0xffffffffu, vmax0, 1));
        vmax0 = fmaxf(vmax0, __shfl_xor_sync(0xffffffffu, vmax0, 2));
        vmax1 = fmaxf(vmax1, __shfl_xor_sync(0xffffffffu, vmax1, 1));
        vmax1 = fmaxf(vmax1, __shfl_xor_sync(0xffffffffu, vmax1, 2));

        const float mn0 = fmaxf(m0, vmax0);
        const float mn1 = fmaxf(m1, vmax1);
        const float c0 = __expf(m0 - mn0);
        const float c1 = __expf(m1 - mn1);
        m0 = mn0; m1 = mn1;

        // P = exp2((s-m)*log2e) via h2exp2, stored as packed fp16 pairs
        const float L2E = 1.44269504088896f;
        uint32_t plo[8], phi[8];
        float rs0 = 0.0f, rs1 = 0.0f;
        #pragma unroll
        for (int j = 0; j < 8; j++) {
            __half2 t0 = __floats2half2_rn((s[j][0] - mn0) * L2E, (s[j][1] - mn0) * L2E);
            __half2 t1 = __floats2half2_rn((s[j][2] - mn1) * L2E, (s[j][3] - mn1) * L2E);
            const __half2 p0 = h2exp2(t0);
            const __half2 p1 = h2exp2(t1);
            plo[j] = *(uint32_t*)&p0;
            phi[j] = *(uint32_t*)&p1;
            const float2 f0 = __half22float2(p0);
            const float2 f1 = __half22float2(p1);
            rs0 += f0.x + f0.y;
            rs1 += f1.x + f1.y;
        }
        rs0 += __shfl_xor_sync(0xffffffffu, rs0, 1);
        rs0 += __shfl_xor_sync(0xffffffffu, rs0, 2);
        rs1 += __shfl_xor_sync(0xffffffffu, rs1, 1);
        rs1 += __shfl_xor_sync(0xffffffffu, rs1, 2);
        l0 = l0 * c0 + rs0;
        l1 = l1 * c1 + rs1;
        #pragma unroll
        for (int j = 0; j < 8; j++) {
            o[j][0] *= c0; o[j][1] *= c0;
            o[j][2] *= c1; o[j][3] *= c1;
        }

        // ---- O += P V : B-fragments from token-major V via ldmatrix.trans ----
        #pragma unroll
        for (int ks = 0; ks < 4; ks++) {
            uint32_t a[4];
            a[0] = plo[2 * ks];
            a[1] = phi[2 * ks];
            a[2] = plo[2 * ks + 1];
            a[3] = phi[2 * ks + 1];
            #pragma unroll
            for (int jb = 0; jb < 4; jb++) {
                uint32_t r0, r1, r2, r3;
                ldmatrix_x4_trans(r0, r1, r2, r3,
                                  vbuf + swadr((uint32_t)(ks * 16 + v_row), 128,
                                               (uint32_t)(jb * 32 + v_col)));
                uint32_t bfr0[2] = {r0, r1}, bfr1[2] = {r2, r3};
                mma16816(o[2 * jb], a, bfr0);
                mma16816(o[2 * jb + 1], a, bfr1);
            }
        }
    }

    // ---- epilogue ----
    const float inv0 = 1.0f / l0;
    const float inv1 = 1.0f / l1;
    const size_t r0g = (size_t)b * Ssz + (size_t)qb * 128 + 16 * w + (lane >> 2);
    const size_t r1g = r0g + 8;
    #pragma unroll
    for (int j = 0; j < 8; j++) {
        const int col = h * 64 + j * 8 + (lane & 3) * 2;
        *(__half2*)(attn2 + r0g * 1024 + col) = __halves2half2(
            __float2half_rn(o[j][0] * inv0), __float2half_rn(o[j][1] * inv0));
        *(__half2*)(attn2 + r1g * 1024 + col) = __halves2half2(
            __float2half_rn(o[j][2] * inv1), __float2half_rn(o[j][3] * inv1));
    }
}

// ===================== fused residual-add + LayerNorm ========================
// MODE 0: A fp32 + B fp16 -> Y2 fp16 only (LN1).
// MODE 1: A fp16 + B fp16 -> Y fp32 only (LN2 / final output).
template<int MODE>
__global__ __launch_bounds__(256)
void add_ln_kernel(const float* __restrict__ Af, const __half* __restrict__ Ah,
                   const __half* __restrict__ Bv,
                   const float* __restrict__ g, const float* __restrict__ be,
                   float* __restrict__ Y, __half* __restrict__ Y2)
{
    const int row = blockIdx.x;
    const int tid = threadIdx.x;
    float a0, a1, a2, a3;
    if (MODE == 0) {
        const float4 av = ((const float4*)(Af + (size_t)row * Esz))[tid];
        a0 = av.x; a1 = av.y; a2 = av.z; a3 = av.w;
    } else {
        const __half2 ah0 = ((const __half2*)(Ah + (size_t)row * Esz))[tid * 2];
        const __half2 ah1 = ((const __half2*)(Ah + (size_t)row * Esz))[tid * 2 + 1];
        const float2 af0 = __half22float2(ah0);
        const float2 af1 = __half22float2(ah1);
        a0 = af0.x; a1 = af0.y; a2 = af1.x; a3 = af1.y;
    }
    const __half2 b0 = ((const __half2*)(Bv + (size_t)row * Esz))[tid * 2];
    const __half2 b1 = ((const __half2*)(Bv + (size_t)row * Esz))[tid * 2 + 1];
    const float2 bf0 = __half22float2(b0);
    const float2 bf1 = __half22float2(b1);
    const float v0 = a0 + bf0.x, v1 = a1 + bf0.y, v2 = a2 + bf1.x, v3 = a3 + bf1.y;

    float s = v0 + v1 + v2 + v3;
    float s2 = v0 * v0 + v1 * v1 + v2 * v2 + v3 * v3;
    #pragma unroll
    for (int o = 16; o; o >>= 1) {
        s += __shfl_xor_sync(0xffffffffu, s, o);
        s2 += __shfl_xor_sync(0xffffffffu, s2, o);
    }
    __shared__ float ss[8], ss2[8];
    const int w = tid >> 5, ln = tid & 31;
    if (ln == 0) { ss[w] = s; ss2[w] = s2; }
    __syncthreads();
    if (tid < 8) {
        s = ss[tid]; s2 = ss2[tid];
        #pragma unroll
        for (int o = 4; o; o >>= 1) {
            s += __shfl_xor_sync(0x000000ffu, s, o);
            s2 += __shfl_xor_sync(0x000000ffu, s2, o);
        }
        if (tid == 0) { ss[0] = s; ss2[0] = s2; }
    }
    __syncthreads();
    const float mean = ss[0] * (1.0f / Esz);
    const float var = ss2[0] * (1.0f / Esz) - mean * mean;
    const float rstd = rsqrtf(var + 1e-5f);

    const float4 gv = ((const float4*)g)[tid];
    const float4 bev = ((const float4*)be)[tid];
    float o4x = (v0 - mean) * rstd * gv.x + bev.x;
    float o4y = (v1 - mean) * rstd * gv.y + bev.y;
    float o4z = (v2 - mean) * rstd * gv.z + bev.z;
    float o4w = (v3 - mean) * rstd * gv.w + bev.w;

    if (MODE == 0) {
        __half* base = Y2 + (size_t)row * 1024 + tid * 4;
        *(__half2*)(base) = __halves2half2(__float2half_rn(o4x), __float2half_rn(o4y));
        *(__half2*)(base + 2) = __halves2half2(__float2half_rn(o4z), __float2half_rn(o4w));
    } else {
        ((float4*)(Y + (size_t)row * Esz))[tid] = make_float4(o4x, o4y, o4z, o4w);
    }
}

// ===================== launch ================================================
extern "C" void kernel_launch(void* const* d_in, const int* in_sizes, int n_in,
                              void* d_out, int out_size)
{
    (void)in_sizes; (void)n_in; (void)out_size;
    const float* x     = (const float*)d_in[0];
    const float* w_qkv = (const float*)d_in[1];
    const float* b_qkv = (const float*)d_in[2];
    const float* w_out = (const float*)d_in[3];
    const float* b_out = (const float*)d_in[4];
    const float* g1    = (const float*)d_in[5];
    const float* beta1 = (const float*)d_in[6];
    const float* w_fc1 = (const float*)d_in[7];
    const float* b_fc1 = (const float*)d_in[8];
    const float* w_fc2 = (const float*)d_in[9];
    const float* b_fc2 = (const float*)d_in[10];
    const float* g2    = (const float*)d_in[11];
    const float* beta2 = (const float*)d_in[12];

    __half *proj16, *ff16, *q2, *k2, *v2, *attn2, *x2, *x12, *h2, *wq2, *wo2, *w12, *w22;
    cudaGetSymbolAddress((void**)&proj16, g_proj16);
    cudaGetSymbolAddress((void**)&ff16,   g_ff16);
    cudaGetSymbolAddress((void**)&q2,     g_q2);
    cudaGetSymbolAddress((void**)&k2,     g_k2);
    cudaGetSymbolAddress((void**)&v2,     g_v2);
    cudaGetSymbolAddress((void**)&attn2,  g_attn2);
    cudaGetSymbolAddress((void**)&x2,     g_x2);
    cudaGetSymbolAddress((void**)&x12,    g_x12);
    cudaGetSymbolAddress((void**)&h2,     g_h2);
    cudaGetSymbolAddress((void**)&wq2,    g_wqkv2);
    cudaGetSymbolAddress((void**)&wo2,    g_wout2);
    cudaGetSymbolAddress((void**)&w12,    g_wfc12);
    cudaGetSymbolAddress((void**)&w22,    g_wfc22);

    cudaFuncSetAttribute(flash_mma_kernel, cudaFuncAttributeMaxDynamicSharedMemorySize, AT_SMEM);
    cudaFuncSetAttribute(gemm_mma_kernel<1>, cudaFuncAttributeMaxDynamicSharedMemorySize, GEMM_SMEM);
    cudaFuncSetAttribute(gemm_mma_kernel<2>, cudaFuncAttributeMaxDynamicSharedMemorySize, GEMM_SMEM);
    cudaFuncSetAttribute(gemm_mma_kernel<3>, cudaFuncAttributeMaxDynamicSharedMemorySize, GEMM_SMEM);

    // fork: non-critical weight converts run on the side stream, overlapping
    // the critical-path converts + qkv GEMM + attention.
    cudaEventRecord(g_side.fork, 0);
    cudaStreamWaitEvent(g_side.s, g_side.fork, 0);
    cvt_rest_kernel<<<1024, 256, 0, g_side.s>>>(w_out, w_fc1, w_fc2, wo2, w12, w22);
    cudaEventRecord(g_side.join, g_side.s);

    // critical path (default stream)
    cvt_crit_kernel<<<1024, 256>>>(w_qkv, x, wq2, x2);
    // 1) qkv = x @ w_qkv^T + b_qkv  -> q2/k2/v2 (all natural fp16)
    gemm_mma_kernel<1><<<dim3(3 * Esz / 128, Msz / 128), 128, GEMM_SMEM>>>(
        x2, wq2, b_qkv, nullptr, q2, k2, v2, 3 * Esz, Esz, Esz, Esz);
    // 2) attention -> attn2
    flash_mma_kernel<<<dim3(Ssz / 128, Hsz, Bsz), 256, AT_SMEM>>>(q2, k2, v2, attn2);

    // join: proj needs wo2 (and later fc1/fc2 weights)
    cudaStreamWaitEvent(0, g_side.join, 0);

    // 3) proj16 = fp16(attn @ w_out^T + b_out)
    gemm_mma_kernel<3><<<dim3(Esz / 128, Msz / 128), 128, GEMM_SMEM>>>(
        attn2, wo2, b_out, proj16, nullptr, nullptr, nullptr, Esz, Esz, Esz, Esz);
    // 4) x12 = fp16(LN(x + proj16))
    add_ln_kernel<0><<<Msz, 256>>>(x, nullptr, proj16, g1, beta1, nullptr, x12);
    // 5) h2 = fp16(gelu(x12 @ w_fc1^T + b_fc1))
    gemm_mma_kernel<2><<<dim3(FFsz / 128, Msz / 128), 128, GEMM_SMEM>>>(
        x12, w12, b_fc1, h2, nullptr, nullptr, nullptr, FFsz, Esz, Esz, Esz);
    // 6) ff16 = fp16(h @ w_fc2^T + b_fc2)
    gemm_mma_kernel<3><<<dim3(Esz / 128, Msz / 128), 128, GEMM_SMEM>>>(
        h2, w22, b_fc2, ff16, nullptr, nullptr, nullptr, Esz, FFsz, FFsz, FFsz);
    // 7) out = LN(x12 + ff16)   (fp32 output)
    add_ln_kernel<1><<<Msz, 256>>>(nullptr, x12, ff16, g2, beta2, (float*)d_out, nullptr);
}

// round 14
// speedup vs baseline: 1.0413x; 1.0413x over previous
#include <cuda_runtime.h>
#include <cuda_fp16.h>
#include <math.h>
#include <stdint.h>

// Problem dims (fixed by the reference)
#define Bsz 2
#define Ssz 2048
#define Esz 1024
#define Hsz 16
#define Dsz 64
#define FFsz 4096
#define Msz (Bsz*Ssz)   // 4096 tokens

// ===================== helpers ===============================================
__device__ __forceinline__ uint32_t smem_to_u32(const void* p) {
    uint32_t a;
    asm("{ .reg .u64 t; cvta.to.shared.u64 t, %1; cvt.u32.u64 %0, t; }" : "=r"(a) : "l"(p));
    return a;
}
#define CPASYNC16(saddr, gptr) \
    asm volatile("cp.async.cg.shared.global [%0], [%1], 16;" :: "r"((uint32_t)(saddr)), "l"(gptr))
#define CPASYNC_COMMIT() asm volatile("cp.async.commit_group;" ::: "memory")
#define CPASYNC_WAIT2() asm volatile("cp.async.wait_group 2;" ::: "memory")
#define CPASYNC_WAIT1() asm volatile("cp.async.wait_group 1;" ::: "memory")
#define CPASYNC_WAIT0() asm volatile("cp.async.wait_group 0;" ::: "memory")

__device__ __forceinline__ void ldmatrix_x4(uint32_t& r0, uint32_t& r1, uint32_t& r2, uint32_t& r3,
                                            uint32_t addr) {
    asm volatile("ldmatrix.sync.aligned.m8n8.x4.shared.b16 {%0,%1,%2,%3}, [%4];"
        : "=r"(r0), "=r"(r1), "=r"(r2), "=r"(r3) : "r"(addr));
}
__device__ __forceinline__ void ldmatrix_x4_trans(uint32_t& r0, uint32_t& r1, uint32_t& r2, uint32_t& r3,
                                                  uint32_t addr) {
    asm volatile("ldmatrix.sync.aligned.m8n8.x4.trans.shared.b16 {%0,%1,%2,%3}, [%4];"
        : "=r"(r0), "=r"(r1), "=r"(r2), "=r"(r3) : "r"(addr));
}
__device__ __forceinline__ void mma16816(float* d, const uint32_t* a, const uint32_t* b) {
    asm volatile("mma.sync.aligned.m16n8k16.row.col.f32.f16.f16.f32 "
        "{%0,%1,%2,%3}, {%4,%5,%6,%7}, {%8,%9}, {%0,%1,%2,%3};"
        : "+f"(d[0]), "+f"(d[1]), "+f"(d[2]), "+f"(d[3])
        : "r"(a[0]), "r"(a[1]), "r"(a[2]), "r"(a[3]), "r"(b[0]), "r"(b[1]));
}
// swizzled address: row-major, row bytes rb (multiple of 128), XOR within 128B blocks
__device__ __forceinline__ uint32_t swadr(uint32_t row, uint32_t rb, uint32_t c) {
    return row * rb + (c & ~127u) + ((c & 127u) ^ ((row & 7u) * 16u));
}

// ===================== scratch (device globals) ==============================
__device__ __half g_proj16[(size_t)Msz * Esz];
__device__ __half g_ff16[(size_t)Msz * Esz];
__device__ __half g_q2[(size_t)Msz * Esz];            // [tok][h][d]
__device__ __half g_k2[(size_t)Msz * Esz];            // [tok][h][d]
__device__ __half g_v2[(size_t)Msz * Esz];            // [tok][h][d]  (natural)
__device__ __half g_attn2[(size_t)Msz * Esz];
__device__ __half g_x2[(size_t)Msz * Esz];
__device__ __half g_x12[(size_t)Msz * Esz];
__device__ __half g_h2[(size_t)Msz * FFsz];
__device__ __half g_wqkv2[(size_t)(3 * Esz) * Esz];
__device__ __half g_wout2[(size_t)Esz * Esz];
__device__ __half g_wfc12[(size_t)FFsz * Esz];
__device__ __half g_wfc22[(size_t)Esz * FFsz];

// ===================== fused fp32->fp16 convert (all tensors) ================
__device__ __forceinline__ void cvt_seg(const float* __restrict__ s, __half* __restrict__ d,
                                        int n8, int base, int stride)
{
    for (int i = base; i < n8; i += stride) {
        const float4 f0 = ((const float4*)s)[2 * i];
        const float4 f1 = ((const float4*)s)[2 * i + 1];
        const __half2 h0 = __floats2half2_rn(f0.x, f0.y);
        const __half2 h1 = __floats2half2_rn(f0.z, f0.w);
        const __half2 h2 = __floats2half2_rn(f1.x, f1.y);
        const __half2 h3 = __floats2half2_rn(f1.z, f1.w);
        uint4 o;
        o.x = *(const uint32_t*)&h0;
        o.y = *(const uint32_t*)&h1;
        o.z = *(const uint32_t*)&h2;
        o.w = *(const uint32_t*)&h3;
        ((uint4*)d)[i] = o;
    }
}
__global__ __launch_bounds__(256)
void cvt_all_kernel(const float* w_qkv, const float* w_out, const float* w_fc1,
                    const float* w_fc2, const float* x,
                    __half* wq2, __half* wo2, __half* w12, __half* w22, __half* x2)
{
    const int base = blockIdx.x * 256 + threadIdx.x;
    const int stride = gridDim.x * 256;
    cvt_seg(w_qkv, wq2, (3 * Esz * Esz) / 8, base, stride);
    cvt_seg(w_out, wo2, (Esz * Esz) / 8, base, stride);
    cvt_seg(w_fc1, w12, (FFsz * Esz) / 8, base, stride);
    cvt_seg(w_fc2, w22, (Esz * FFsz) / 8, base, stride);
    cvt_seg(x, x2, (Msz * Esz) / 8, base, stride);
}

// ===================== HMMA fp16 GEMM (128x128 tile, 128 thr, 64x64 warp) ====
// C = A*B^T + bias. MODE 1: qkv split (q/k/v natural fp16).
// MODE 2: GELU + fp16 out. MODE 3: fp16 out (no act).
#define NBUF 3
#define STAGE_BYTES (128 * 128)
#define STAGE_AB (2 * STAGE_BYTES)
#define GEMM_SMEM (NBUF * STAGE_AB)

template<int MODE>
__global__ __launch_bounds__(128, 2)
void gemm_mma_kernel(const __half* __restrict__ A, const __half* __restrict__ Bm,
                     const float* __restrict__ bias,
                     __half* __restrict__ C3,
                     __half* __restrict__ q2p, __half* __restrict__ k2p, __half* __restrict__ v2p,
                     int N, int K2, int lda, int ldb)
{
    extern __shared__ __align__(1024) char smem[];
    const uint32_t sbase = smem_to_u32(smem);
    const int tid = threadIdx.x;
    const int lane = tid & 31;
    const int wid = tid >> 5;
    const int wm = wid & 1;        // 2 m-warps (64 rows each)
    const int wn = wid >> 1;       // 2 n-warps (64 cols each)
    const int bx = blockIdx.x, by = blockIdx.y;

    // fill: 8 x 16B chunks per thread per operand per stage (128 threads)
    uint32_t st_off[8];
    const char* Agp[8];
    const char* Bgp[8];
    #pragma unroll
    for (int t = 0; t < 8; t++) {
        const int idx = tid + t * 128;
        const int row = idx >> 3, c = (idx & 7) * 16;
        st_off[t] = (uint32_t)(row * 128 + (c ^ ((row & 7) * 16)));
        Agp[t] = (const char*)A + ((size_t)(by * 128 + row) * lda + (idx & 7) * 8) * 2;
        Bgp[t] = (const char*)Bm + ((size_t)(bx * 128 + row) * ldb + (idx & 7) * 8) * 2;
    }

    const uint32_t colxor = (uint32_t)((lane & 7) * 16);
    const uint32_t a_rowbase = (uint32_t)((wm * 64 + (lane & 15)) * 128);
    const uint32_t a_part = (uint32_t)((lane >> 4) * 16);
    const uint32_t b_rowbase = (uint32_t)((wn * 64 + ((lane >> 4) << 3) + (lane & 7)) * 128);
    const uint32_t b_part = (uint32_t)(((lane >> 3) & 1) * 16);

    float acc[4][8][4];
    #pragma unroll
    for (int i = 0; i < 4; i++)
        #pragma unroll
        for (int j = 0; j < 8; j++)
            #pragma unroll
            for (int u = 0; u < 4; u++) acc[i][j][u] = 0.0f;

    const int S = K2 / 64;

    #pragma unroll
    for (int p = 0; p < NBUF; p++) {
        const uint32_t ab = sbase + p * STAGE_AB;
        const uint32_t bb = ab + STAGE_BYTES;
        #pragma unroll
        for (int t = 0; t < 8; t++) {
            CPASYNC16(ab + st_off[t], Agp[t] + (size_t)p * 128);
            CPASYNC16(bb + st_off[t], Bgp[t] + (size_t)p * 128);
        }
        CPASYNC_COMMIT();
    }

    #pragma unroll 1
    for (int s = 0; s < S; s++) {
        if (s + NBUF <= S) CPASYNC_WAIT2();
        else               CPASYNC_WAIT0();
        __syncthreads();
        const uint32_t ab = sbase + (s % NBUF) * STAGE_AB;
        const uint32_t bb = ab + STAGE_BYTES;

        #pragma unroll
        for (int k = 0; k < 4; k++) {
            const uint32_t kb = (uint32_t)(k * 32);
            uint32_t a[4][4], b[8][2];
            #pragma unroll
            for (int i = 0; i < 4; i++)
                ldmatrix_x4(a[i][0], a[i][1], a[i][2], a[i][3],
                            ab + a_rowbase + (uint32_t)(i * 2048) + ((kb + a_part) ^ colxor));
            #pragma unroll
            for (int jp = 0; jp < 4; jp++) {
                uint32_t r0, r1, r2, r3;
                ldmatrix_x4(r0, r1, r2, r3,
                            bb + b_rowbase + (uint32_t)(jp * 2048) + ((kb + b_part) ^ colxor));
                b[2 * jp][0] = r0; b[2 * jp][1] = r1;
                b[2 * jp + 1][0] = r2; b[2 * jp + 1][1] = r3;
            }
            #pragma unroll
            for (int i = 0; i < 4; i++)
                #pragma unroll
                for (int j = 0; j < 8; j++)
                    mma16816(acc[i][j], a[i], b[j]);
        }
        __syncthreads();
        if (s + NBUF < S) {
            const int sn = s + NBUF;
            #pragma unroll
            for (int t = 0; t < 8; t++) {
                CPASYNC16(ab + st_off[t], Agp[t] + (size_t)sn * 128);
                CPASYNC16(bb + st_off[t], Bgp[t] + (size_t)sn * 128);
            }
            CPASYNC_COMMIT();
        }
    }

    // ---- epilogue ----
    const int row0 = by * 128 + wm * 64 + (lane >> 2);
    const int col0 = bx * 128 + wn * 64 + (lane & 3) * 2;
    #pragma unroll
    for (int j = 0; j < 8; j++) {
        const int col = col0 + j * 8;
        const float2 bv = *(const float2*)&bias[col];
        #pragma unroll
        for (int i = 0; i < 4; i++) {
            #pragma unroll
            for (int half = 0; half < 2; half++) {
                const int row = row0 + i * 16 + half * 8;
                float v0 = acc[i][j][half * 2 + 0] + bv.x;
                float v1 = acc[i][j][half * 2 + 1] + bv.y;
                if (MODE == 2) {
                    v0 = 0.5f * v0 * (1.0f + erff(v0 * 0.70710678118654752f));
                    v1 = 0.5f * v1 * (1.0f + erff(v1 * 0.70710678118654752f));
                    *(__half2*)(C3 + (size_t)row * N + col) =
                        __halves2half2(__float2half_rn(v0), __float2half_rn(v1));
                } else if (MODE == 3) {
                    *(__half2*)(C3 + (size_t)row * N + col) =
                        __halves2half2(__float2half_rn(v0), __float2half_rn(v1));
                } else {  // MODE 1: qkv split epilogue (all natural layouts)
                    const int sec = col >> 10;
                    const int within = col & 1023;
                    const __half2 hv = __halves2half2(__float2half_rn(v0), __float2half_rn(v1));
                    if (sec == 0)      *(__half2*)(q2p + (size_t)row * 1024 + within) = hv;
                    else if (sec == 1) *(__half2*)(k2p + (size_t)row * 1024 + within) = hv;
                    else               *(__half2*)(v2p + (size_t)row * 1024 + within) = hv;
                }
            }
        }
    }
}

// ===================== FA2 flash attention (Q64, 4 CTAs/SM) ==================
// grid (S/64, H, B) = 1024 CTAs, 128 threads (4 warps, each 16 rows x 64 n).
// Register softmax via h2exp2; fp16 P doubles as PV A-operand.
// V natural [tok][d]; PV B-fragments via ldmatrix.trans. Triple-buffered K/V.
#define SQ2 0                    // 8KB (64 rows x 128B)
#define SKV 8192                 // 3 x (8KB K + 8KB V)
#define AT_SMEM (8192 + 3 * 16384)   // 57344

__global__ __launch_bounds__(128, 4)
void flash_mma_kernel(const __half* __restrict__ q2, const __half* __restrict__ k2,
                      const __half* __restrict__ v2, __half* __restrict__ attn2)
{
    extern __shared__ __align__(1024) char sm_[];
    const uint32_t sb = smem_to_u32(sm_);

    const int tid = threadIdx.x, lane = tid & 31, w = tid >> 5;
    const int qb = blockIdx.x, h = blockIdx.y, b = blockIdx.z;
    const int NKB = Ssz / 64;   // 32

    const char* qsrc = (const char*)q2 + ((size_t)(b * Ssz + qb * 64) * 1024 + h * 64) * 2;
    const char* ksrc = (const char*)k2 + ((size_t)b * Ssz * 1024 + h * 64) * 2;
    const char* vsrc = (const char*)v2 + ((size_t)b * Ssz * 1024 + h * 64) * 2;

    // ---- prologue: Q + (K,V)(0) [group0], (K,V)(1) [group1] ----
    #pragma unroll
    for (int it = 0; it < 4; it++) {
        const int idx = tid + it * 128;
        const int r = idx >> 3;
        const int c = (idx & 7) * 16;
        CPASYNC16(sb + SQ2 + swadr(r, 128, c), qsrc + (size_t)r * 2048 + c);
    }
    #pragma unroll
    for (int p = 0; p < 2; p++) {
        const uint32_t ko = SKV + p * 16384;
        const uint32_t vo = ko + 8192;
        #pragma unroll
        for (int it = 0; it < 4; it++) {
            const int idx = tid + it * 128;
            const int r = idx >> 3;
            const int c = (idx & 7) * 16;
            CPASYNC16(sb + ko + swadr(r, 128, c), ksrc + (size_t)(p * 64 + r) * 2048 + c);
            CPASYNC16(sb + vo + swadr(r, 128, c), vsrc + (size_t)(p * 64 + r) * 2048 + c);
        }
        CPASYNC_COMMIT();
    }

    const int a_row = lane & 15;
    const int a_part = (lane >> 4) * 16;
    const int b_rowo = ((lane >> 4) << 3) + (lane & 7);
    const int b_part = ((lane >> 3) & 1) * 16;
    // trans-ldmatrix lane map (B from token-major V tile)
    const int v_row = lane & 15;
    const int v_col = (lane >> 4) * 16;

    uint32_t q[4][4];
    float o[8][4];
    #pragma unroll
    for (int j = 0; j < 8; j++)
        #pragma unroll
        for (int u = 0; u < 4; u++) o[j][u] = 0.0f;
    float m0 = -INFINITY, m1 = -INFINITY, l0 = 0.0f, l1 = 0.0f;

    #pragma unroll 1
    for (int kb = 0; kb < NKB; kb++) {
        if (kb + 1 < NKB) CPASYNC_WAIT1();
        else              CPASYNC_WAIT0();
        __syncthreads();   // (a) K/V(kb) visible; (b) all warps past kb-1 reads

        // prefetch (kb+2) into buffer (kb+2)%3 — last read at iter kb-1
        if (kb + 2 < NKB) {
            const uint32_t ko = SKV + ((kb + 2) % 3) * 16384;
            const uint32_t vo = ko + 8192;
            #pragma unroll
            for (int it = 0; it < 4; it++) {
                const int idx = tid + it * 128;
                const int r = idx >> 3;
                const int c = (idx & 7) * 16;
                CPASYNC16(sb + ko + swadr(r, 128, c),
                          ksrc + (size_t)((kb + 2) * 64 + r) * 2048 + c);
                CPASYNC16(sb + vo + swadr(r, 128, c),
                          vsrc + (size_t)((kb + 2) * 64 + r) * 2048 + c);
            }
            CPASYNC_COMMIT();
        }

        if (kb == 0) {
            // load Q fragments once; pre-scale by 1/8 (exact in fp16)
            const __half2 sc = __half2half2(__float2half(0.125f));
            #pragma unroll
            for (int ks = 0; ks < 4; ks++) {
                ldmatrix_x4(q[ks][0], q[ks][1], q[ks][2], q[ks][3],
                            sb + SQ2 + swadr((uint32_t)(16 * w + a_row), 128,
                                             (uint32_t)(ks * 32 + a_part)));
                #pragma unroll
                for (int u = 0; u < 4; u++) {
                    __half2 t = *(__half2*)&q[ks][u];
                    t = __hmul2(t, sc);
                    q[ks][u] = *(uint32_t*)&t;
                }
            }
        }

        const uint32_t kbuf = sb + SKV + (kb % 3) * 16384;
        const uint32_t vbuf = kbuf + 8192;

        // ---- S = Q K^T : warp tile 16(m) x 64(n tokens), 4 k-steps ----
        float s[8][4];
        #pragma unroll
        for (int j = 0; j < 8; j++)
            #pragma unroll
            for (int u = 0; u < 4; u++) s[j][u] = 0.0f;

        #pragma unroll
        for (int ks = 0; ks < 4; ks++) {
            #pragma unroll
            for (int jb = 0; jb < 4; jb++) {
                uint32_t r0, r1, r2, r3;
                ldmatrix_x4(r0, r1, r2, r3,
                            kbuf + swadr((uint32_t)(jb * 16 + b_rowo), 128,
                                         (uint32_t)(ks * 32 + b_part)));
                uint32_t bfr0[2] = {r0, r1}, bfr1[2] = {r2, r3};
                mma16816(s[2 * jb], q[ks], bfr0);
                mma16816(s[2 * jb + 1], q[ks], bfr1);
            }
        }

        // ---- register online softmax (rows r0 = lane>>2, r1 = r0+8) ----
        float vmax0 = -INFINITY, vmax1 = -INFINITY;
        #pragma unroll
        for (int j = 0; j < 8; j++) {
            vmax0 = fmaxf(vmax0, fmaxf(s[j][0], s[j][1]));
            vmax1 = fmaxf(vmax1, fmaxf(s[j][2], s[j][3]));
        }
        vmax0 = fmaxf(vmax0, __shfl_xor_sync(0xffffffffu, vmax0, 1));
        vmax0 = fmaxf(vmax0, __shfl_xor_sync(0xffffffffu, vmax0, 2));
        vmax1 = fmaxf(vmax1, __shfl_xor_sync(0xffffffffu, vmax1, 1));
        vmax1 = fmaxf(vmax1, __shfl_xor_sync(0xffffffffu, vmax1, 2));

        const float mn0 = fmaxf(m0, vmax0);
        const float mn1 = fmaxf(m1, vmax1);
        const float c0 = __expf(m0 - mn0);
        const float c1 = __expf(m1 - mn1);
        m0 = mn0; m1 = mn1;

        // P = exp2((s-m)*log2e) via h2exp2, stored as packed fp16 pairs
        const float L2E = 1.44269504088896f;
        uint32_t plo[8], phi[8];
        float rs0 = 0.0f, rs1 = 0.0f;
        #pragma unroll
        for (int j = 0; j < 8; j++) {
            __half2 t0 = __floats2half2_rn((s[j][0] - mn0) * L2E, (s[j][1] - mn0) * L2E);
            __half2 t1 = __floats2half2_rn((s[j][2] - mn1) * L2E, (s[j][3] - mn1) * L2E);
            const __half2 p0 = h2exp2(t0);
            const __half2 p1 = h2exp2(t1);
            plo[j] = *(uint32_t*)&p0;
            phi[j] = *(uint32_t*)&p1;
            const float2 f0 = __half22float2(p0);
            const float2 f1 = __half22float2(p1);
            rs0 += f0.x + f0.y;
            rs1 += f1.x + f1.y;
        }
        rs0 += __shfl_xor_sync(0xffffffffu, rs0, 1);
        rs0 += __shfl_xor_sync(0xffffffffu, rs0, 2);
        rs1 += __shfl_xor_sync(0xffffffffu, rs1, 1);
        rs1 += __shfl_xor_sync(0xffffffffu, rs1, 2);
        l0 = l0 * c0 + rs0;
        l1 = l1 * c1 + rs1;
        #pragma unroll
        for (int j = 0; j < 8; j++) {
            o[j][0] *= c0; o[j][1] *= c0;
            o[j][2] *= c1; o[j][3] *= c1;
        }

        // ---- O += P V : B-fragments from token-major V via ldmatrix.trans ----
        #pragma unroll
        for (int ks = 0; ks < 4; ks++) {
            uint32_t a[4];
            a[0] = plo[2 * ks];
            a[1] = phi[2 * ks];
            a[2] = plo[2 * ks + 1];
            a[3] = phi[2 * ks + 1];
            #pragma unroll
            for (int jb = 0; jb < 4; jb++) {
                uint32_t r0, r1, r2, r3;
                ldmatrix_x4_trans(r0, r1, r2, r3,
                                  vbuf + swadr((uint32_t)(ks * 16 + v_row), 128,
                                               (uint32_t)(jb * 32 + v_col)));
                uint32_t bfr0[2] = {r0, r1}, bfr1[2] = {r2, r3};
                mma16816(o[2 * jb], a, bfr0);
                mma16816(o[2 * jb + 1], a, bfr1);
            }
        }
    }

    // ---- epilogue ----
    const float inv0 = 1.0f / l0;
    const float inv1 = 1.0f / l1;
    const size_t r0g = (size_t)b * Ssz + (size_t)qb * 64 + 16 * w + (lane >> 2);
    const size_t r1g = r0g + 8;
    #pragma unroll
    for (int j = 0; j < 8; j++) {
        const int col = h * 64 + j * 8 + (lane & 3) * 2;
        *(__half2*)(attn2 + r0g * 1024 + col) = __halves2half2(
            __float2half_rn(o[j][0] * inv0), __float2half_rn(o[j][1] * inv0));
        *(__half2*)(attn2 + r1g * 1024 + col) = __halves2half2(
            __float2half_rn(o[j][2] * inv1), __float2half_rn(o[j][3] * inv1));
    }
}

// ===================== fused residual-add + LayerNorm ========================
// MODE 0: A fp32 + B fp16 -> Y2 fp16 only (LN1).
// MODE 1: A fp16 + B fp16 -> Y fp32 only (LN2 / final output).
template<int MODE>
__global__ __launch_bounds__(256)
void add_ln_kernel(const float* __restrict__ Af, const __half* __restrict__ Ah,
                   const __half* __restrict__ Bv,
                   const float* __restrict__ g, const float* __restrict__ be,
                   float* __restrict__ Y, __half* __restrict__ Y2)
{
    const int row = blockIdx.x;
    const int tid = threadIdx.x;
    float a0, a1, a2, a3;
    if (MODE == 0) {
        const float4 av = ((const float4*)(Af + (size_t)row * Esz))[tid];
        a0 = av.x; a1 = av.y; a2 = av.z; a3 = av.w;
    } else {
        const __half2 ah0 = ((const __half2*)(Ah + (size_t)row * Esz))[tid * 2];
        const __half2 ah1 = ((const __half2*)(Ah + (size_t)row * Esz))[tid * 2 + 1];
        const float2 af0 = __half22float2(ah0);
        const float2 af1 = __half22float2(ah1);
        a0 = af0.x; a1 = af0.y; a2 = af1.x; a3 = af1.y;
    }
    const __half2 b0 = ((const __half2*)(Bv + (size_t)row * Esz))[tid * 2];
    const __half2 b1 = ((const __half2*)(Bv + (size_t)row * Esz))[tid * 2 + 1];
    const float2 bf0 = __half22float2(b0);
    const float2 bf1 = __half22float2(b1);
    const float v0 = a0 + bf0.x, v1 = a1 + bf0.y, v2 = a2 + bf1.x, v3 = a3 + bf1.y;

    float s = v0 + v1 + v2 + v3;
    float s2 = v0 * v0 + v1 * v1 + v2 * v2 + v3 * v3;
    #pragma unroll
    for (int o = 16; o; o >>= 1) {
        s += __shfl_xor_sync(0xffffffffu, s, o);
        s2 += __shfl_xor_sync(0xffffffffu, s2, o);
    }
    __shared__ float ss[8], ss2[8];
    const int w = tid >> 5, ln = tid & 31;
    if (ln == 0) { ss[w] = s; ss2[w] = s2; }
    __syncthreads();
    if (tid < 8) {
        s = ss[tid]; s2 = ss2[tid];
        #pragma unroll
        for (int o = 4; o; o >>= 1) {
            s += __shfl_xor_sync(0x000000ffu, s, o);
            s2 += __shfl_xor_sync(0x000000ffu, s2, o);
        }
        if (tid == 0) { ss[0] = s; ss2[0] = s2; }
    }
    __syncthreads();
    const float mean = ss[0] * (1.0f / Esz);
    const float var = ss2[0] * (1.0f / Esz) - mean * mean;
    const float rstd = rsqrtf(var + 1e-5f);

    const float4 gv = ((const float4*)g)[tid];
    const float4 bev = ((const float4*)be)[tid];
    float o4x = (v0 - mean) * rstd * gv.x + bev.x;
    float o4y = (v1 - mean) * rstd * gv.y + bev.y;
    float o4z = (v2 - mean) * rstd * gv.z + bev.z;
    float o4w = (v3 - mean) * rstd * gv.w + bev.w;

    if (MODE == 0) {
        __half* base = Y2 + (size_t)row * 1024 + tid * 4;
        *(__half2*)(base) = __halves2half2(__float2half_rn(o4x), __float2half_rn(o4y));
        *(__half2*)(base + 2) = __halves2half2(__float2half_rn(o4z), __float2half_rn(o4w));
    } else {
        ((float4*)(Y + (size_t)row * Esz))[tid] = make_float4(o4x, o4y, o4z, o4w);
    }
}

// ===================== launch ================================================
extern "C" void kernel_launch(void* const* d_in, const int* in_sizes, int n_in,
                              void* d_out, int out_size)
{
    (void)in_sizes; (void)n_in; (void)out_size;
    const float* x     = (const float*)d_in[0];
    const float* w_qkv = (const float*)d_in[1];
    const float* b_qkv = (const float*)d_in[2];
    const float* w_out = (const float*)d_in[3];
    const float* b_out = (const float*)d_in[4];
    const float* g1    = (const float*)d_in[5];
    const float* beta1 = (const float*)d_in[6];
    const float* w_fc1 = (const float*)d_in[7];
    const float* b_fc1 = (const float*)d_in[8];
    const float* w_fc2 = (const float*)d_in[9];
    const float* b_fc2 = (const float*)d_in[10];
    const float* g2    = (const float*)d_in[11];
    const float* beta2 = (const float*)d_in[12];

    __half *proj16, *ff16, *q2, *k2, *v2, *attn2, *x2, *x12, *h2, *wq2, *wo2, *w12, *w22;
    cudaGetSymbolAddress((void**)&proj16, g_proj16);
    cudaGetSymbolAddress((void**)&ff16,   g_ff16);
    cudaGetSymbolAddress((void**)&q2,     g_q2);
    cudaGetSymbolAddress((void**)&k2,     g_k2);
    cudaGetSymbolAddress((void**)&v2,     g_v2);
    cudaGetSymbolAddress((void**)&attn2,  g_attn2);
    cudaGetSymbolAddress((void**)&x2,     g_x2);
    cudaGetSymbolAddress((void**)&x12,    g_x12);
    cudaGetSymbolAddress((void**)&h2,     g_h2);
    cudaGetSymbolAddress((void**)&wq2,    g_wqkv2);
    cudaGetSymbolAddress((void**)&wo2,    g_wout2);
    cudaGetSymbolAddress((void**)&w12,    g_wfc12);
    cudaGetSymbolAddress((void**)&w22,    g_wfc22);

    cudaFuncSetAttribute(flash_mma_kernel, cudaFuncAttributeMaxDynamicSharedMemorySize, AT_SMEM);
    cudaFuncSetAttribute(gemm_mma_kernel<1>, cudaFuncAttributeMaxDynamicSharedMemorySize, GEMM_SMEM);
    cudaFuncSetAttribute(gemm_mma_kernel<2>, cudaFuncAttributeMaxDynamicSharedMemorySize, GEMM_SMEM);
    cudaFuncSetAttribute(gemm_mma_kernel<3>, cudaFuncAttributeMaxDynamicSharedMemorySize, GEMM_SMEM);

    // 0) all fp32->fp16 converts in one kernel (16B vectorized stores)
    cvt_all_kernel<<<2048, 256>>>(w_qkv, w_out, w_fc1, w_fc2, x, wq2, wo2, w12, w22, x2);

    // 1) qkv = x @ w_qkv^T + b_qkv  -> q2/k2/v2 (all natural fp16)
    gemm_mma_kernel<1><<<dim3(3 * Esz / 128, Msz / 128), 128, GEMM_SMEM>>>(
        x2, wq2, b_qkv, nullptr, q2, k2, v2, 3 * Esz, Esz, Esz, Esz);
    // 2) attention -> attn2  (Q64 tiles, 4 CTAs/SM)
    flash_mma_kernel<<<dim3(Ssz / 64, Hsz, Bsz), 128, AT_SMEM>>>(q2, k2, v2, attn2);
    // 3) proj16 = fp16(attn @ w_out^T + b_out)
    gemm_mma_kernel<3><<<dim3(Esz / 128, Msz / 128), 128, GEMM_SMEM>>>(
        attn2, wo2, b_out, proj16, nullptr, nullptr, nullptr, Esz, Esz, Esz, Esz);
    // 4) x12 = fp16(LN(x + proj16))
    add_ln_kernel<0><<<Msz, 256>>>(x, nullptr, proj16, g1, beta1, nullptr, x12);
    // 5) h2 = fp16(gelu(x12 @ w_fc1^T + b_fc1))
    gemm_mma_kernel<2><<<dim3(FFsz / 128, Msz / 128), 128, GEMM_SMEM>>>(
        x12, w12, b_fc1, h2, nullptr, nullptr, nullptr, FFsz, Esz, Esz, Esz);
    // 6) ff16 = fp16(h @ w_fc2^T + b_fc2)
    gemm_mma_kernel<3><<<dim3(Esz / 128, Msz / 128), 128, GEMM_SMEM>>>(
        h2, w22, b_fc2, ff16, nullptr, nullptr, nullptr, Esz, FFsz, FFsz, FFsz);
    // 7) out = LN(x12 + ff16)   (fp32 output)
    add_ln_kernel<1><<<Msz, 256>>>(nullptr, x12, ff16, g2, beta2, (float*)d_out, nullptr);
}

// round 15
// speedup vs baseline: 1.0606x; 1.0185x over previous
#include <cuda_runtime.h>
#include <cuda_fp16.h>
#include <math.h>
#include <stdint.h>

// Problem dims (fixed by the reference)
#define Bsz 2
#define Ssz 2048
#define Esz 1024
#define Hsz 16
#define Dsz 64
#define FFsz 4096
#define Msz (Bsz*Ssz)   // 4096 tokens

// ===================== helpers ===============================================
__device__ __forceinline__ uint32_t smem_to_u32(const void* p) {
    uint32_t a;
    asm("{ .reg .u64 t; cvta.to.shared.u64 t, %1; cvt.u32.u64 %0, t; }" : "=r"(a) : "l"(p));
    return a;
}
#define CPASYNC16(saddr, gptr) \
    asm volatile("cp.async.cg.shared.global [%0], [%1], 16;" :: "r"((uint32_t)(saddr)), "l"(gptr))
#define CPASYNC_COMMIT() asm volatile("cp.async.commit_group;" ::: "memory")
#define CPASYNC_WAIT1() asm volatile("cp.async.wait_group 1;" ::: "memory")
#define CPASYNC_WAIT0() asm volatile("cp.async.wait_group 0;" ::: "memory")

__device__ __forceinline__ void ldmatrix_x4(uint32_t& r0, uint32_t& r1, uint32_t& r2, uint32_t& r3,
                                            uint32_t addr) {
    asm volatile("ldmatrix.sync.aligned.m8n8.x4.shared.b16 {%0,%1,%2,%3}, [%4];"
        : "=r"(r0), "=r"(r1), "=r"(r2), "=r"(r3) : "r"(addr));
}
__device__ __forceinline__ void ldmatrix_x4_trans(uint32_t& r0, uint32_t& r1, uint32_t& r2, uint32_t& r3,
                                                  uint32_t addr) {
    asm volatile("ldmatrix.sync.aligned.m8n8.x4.trans.shared.b16 {%0,%1,%2,%3}, [%4];"
        : "=r"(r0), "=r"(r1), "=r"(r2), "=r"(r3) : "r"(addr));
}
__device__ __forceinline__ void mma16816(float* d, const uint32_t* a, const uint32_t* b) {
    asm volatile("mma.sync.aligned.m16n8k16.row.col.f32.f16.f16.f32 "
        "{%0,%1,%2,%3}, {%4,%5,%6,%7}, {%8,%9}, {%0,%1,%2,%3};"
        : "+f"(d[0]), "+f"(d[1]), "+f"(d[2]), "+f"(d[3])
        : "r"(a[0]), "r"(a[1]), "r"(a[2]), "r"(a[3]), "r"(b[0]), "r"(b[1]));
}
// swizzled address: row-major, row bytes rb (multiple of 128), XOR within 128B blocks
__device__ __forceinline__ uint32_t swadr(uint32_t row, uint32_t rb, uint32_t c) {
    return row * rb + (c & ~127u) + ((c & 127u) ^ ((row & 7u) * 16u));
}

// ===================== scratch (device globals) ==============================
__device__ __half g_proj16[(size_t)Msz * Esz];
__device__ __half g_ff16[(size_t)Msz * Esz];
__device__ __half g_q2[(size_t)Msz * Esz];            // [tok][h][d]
__device__ __half g_k2[(size_t)Msz * Esz];            // [tok][h][d]
__device__ __half g_v2[(size_t)Msz * Esz];            // [tok][h][d]  (natural)
__device__ __half g_attn2[(size_t)Msz * Esz];
__device__ __half g_x2[(size_t)Msz * Esz];
__device__ __half g_x12[(size_t)Msz * Esz];
__device__ __half g_h2[(size_t)Msz * FFsz];
__device__ __half g_wqkv2[(size_t)(3 * Esz) * Esz];
__device__ __half g_wout2[(size_t)Esz * Esz];
__device__ __half g_wfc12[(size_t)FFsz * Esz];
__device__ __half g_wfc22[(size_t)Esz * FFsz];

// ===================== fused fp32->fp16 convert (all tensors) ================
__device__ __forceinline__ void cvt_seg(const float* __restrict__ s, __half* __restrict__ d,
                                        int n8, int base, int stride)
{
    for (int i = base; i < n8; i += stride) {
        const float4 f0 = ((const float4*)s)[2 * i];
        const float4 f1 = ((const float4*)s)[2 * i + 1];
        const __half2 h0 = __floats2half2_rn(f0.x, f0.y);
        const __half2 h1 = __floats2half2_rn(f0.z, f0.w);
        const __half2 h2 = __floats2half2_rn(f1.x, f1.y);
        const __half2 h3 = __floats2half2_rn(f1.z, f1.w);
        uint4 o;
        o.x = *(const uint32_t*)&h0;
        o.y = *(const uint32_t*)&h1;
        o.z = *(const uint32_t*)&h2;
        o.w = *(const uint32_t*)&h3;
        ((uint4*)d)[i] = o;
    }
}
__global__ __launch_bounds__(256)
void cvt_all_kernel(const float* w_qkv, const float* w_out, const float* w_fc1,
                    const float* w_fc2, const float* x,
                    __half* wq2, __half* wo2, __half* w12, __half* w22, __half* x2)
{
    const int base = blockIdx.x * 256 + threadIdx.x;
    const int stride = gridDim.x * 256;
    cvt_seg(w_qkv, wq2, (3 * Esz * Esz) / 8, base, stride);
    cvt_seg(w_out, wo2, (Esz * Esz) / 8, base, stride);
    cvt_seg(w_fc1, w12, (FFsz * Esz) / 8, base, stride);
    cvt_seg(w_fc2, w22, (Esz * FFsz) / 8, base, stride);
    cvt_seg(x, x2, (Msz * Esz) / 8, base, stride);
}

// ===================== HMMA fp16 GEMM (128x128 tile, 128 thr, 64x64 warp) ====
// Single-barrier mainloop (flash-style 2-ahead prefetch, NBUF=3).
// C = A*B^T + bias. MODE 1: qkv split. MODE 2: GELU + fp16 out. MODE 3: fp16.
#define NBUF 3
#define STAGE_BYTES (128 * 128)
#define STAGE_AB (2 * STAGE_BYTES)
#define GEMM_SMEM (NBUF * STAGE_AB)

template<int MODE>
__global__ __launch_bounds__(128, 2)
void gemm_mma_kernel(const __half* __restrict__ A, const __half* __restrict__ Bm,
                     const float* __restrict__ bias,
                     __half* __restrict__ C3,
                     __half* __restrict__ q2p, __half* __restrict__ k2p, __half* __restrict__ v2p,
                     int N, int K2, int lda, int ldb)
{
    extern __shared__ __align__(1024) char smem[];
    const uint32_t sbase = smem_to_u32(smem);
    const int tid = threadIdx.x;
    const int lane = tid & 31;
    const int wid = tid >> 5;
    const int wm = wid & 1;        // 2 m-warps (64 rows each)
    const int wn = wid >> 1;       // 2 n-warps (64 cols each)
    const int bx = blockIdx.x, by = blockIdx.y;

    // fill: 8 x 16B chunks per thread per operand per stage (128 threads)
    uint32_t st_off[8];
    const char* Agp[8];
    const char* Bgp[8];
    #pragma unroll
    for (int t = 0; t < 8; t++) {
        const int idx = tid + t * 128;
        const int row = idx >> 3, c = (idx & 7) * 16;
        st_off[t] = (uint32_t)(row * 128 + (c ^ ((row & 7) * 16)));
        Agp[t] = (const char*)A + ((size_t)(by * 128 + row) * lda + (idx & 7) * 8) * 2;
        Bgp[t] = (const char*)Bm + ((size_t)(bx * 128 + row) * ldb + (idx & 7) * 8) * 2;
    }

    const uint32_t colxor = (uint32_t)((lane & 7) * 16);
    const uint32_t a_rowbase = (uint32_t)((wm * 64 + (lane & 15)) * 128);
    const uint32_t a_part = (uint32_t)((lane >> 4) * 16);
    const uint32_t b_rowbase = (uint32_t)((wn * 64 + ((lane >> 4) << 3) + (lane & 7)) * 128);
    const uint32_t b_part = (uint32_t)(((lane >> 3) & 1) * 16);

    float acc[4][8][4];
    #pragma unroll
    for (int i = 0; i < 4; i++)
        #pragma unroll
        for (int j = 0; j < 8; j++)
            #pragma unroll
            for (int u = 0; u < 4; u++) acc[i][j][u] = 0.0f;

    const int S = K2 / 64;

    // prologue: fill stages 0 and 1 (2 commit groups)
    #pragma unroll
    for (int p = 0; p < 2; p++) {
        const uint32_t ab = sbase + p * STAGE_AB;
        const uint32_t bb = ab + STAGE_BYTES;
        #pragma unroll
        for (int t = 0; t < 8; t++) {
            CPASYNC16(ab + st_off[t], Agp[t] + (size_t)p * 128);
            CPASYNC16(bb + st_off[t], Bgp[t] + (size_t)p * 128);
        }
        CPASYNC_COMMIT();
    }

    #pragma unroll 1
    for (int s = 0; s < S; s++) {
        if (s + 1 < S) CPASYNC_WAIT1();   // fill(s) complete; fill(s+1) may fly
        else           CPASYNC_WAIT0();
        __syncthreads();                   // data visible; all warps past s-1 reads

        // prefetch stage s+2 into buffer (s+2)%3 — last read at iteration s-1
        if (s + 2 < S) {
            const int sn = s + 2;
            const uint32_t ab = sbase + (sn % NBUF) * STAGE_AB;
            const uint32_t bb = ab + STAGE_BYTES;
            #pragma unroll
            for (int t = 0; t < 8; t++) {
                CPASYNC16(ab + st_off[t], Agp[t] + (size_t)sn * 128);
                CPASYNC16(bb + st_off[t], Bgp[t] + (size_t)sn * 128);
            }
            CPASYNC_COMMIT();
        }

        const uint32_t ab = sbase + (s % NBUF) * STAGE_AB;
        const uint32_t bb = ab + STAGE_BYTES;
        #pragma unroll
        for (int k = 0; k < 4; k++) {
            const uint32_t kb = (uint32_t)(k * 32);
            uint32_t a[4][4], b[8][2];
            #pragma unroll
            for (int i = 0; i < 4; i++)
                ldmatrix_x4(a[i][0], a[i][1], a[i][2], a[i][3],
                            ab + a_rowbase + (uint32_t)(i * 2048) + ((kb + a_part) ^ colxor));
            #pragma unroll
            for (int jp = 0; jp < 4; jp++) {
                uint32_t r0, r1, r2, r3;
                ldmatrix_x4(r0, r1, r2, r3,
                            bb + b_rowbase + (uint32_t)(jp * 2048) + ((kb + b_part) ^ colxor));
                b[2 * jp][0] = r0; b[2 * jp][1] = r1;
                b[2 * jp + 1][0] = r2; b[2 * jp + 1][1] = r3;
            }
            #pragma unroll
            for (int i = 0; i < 4; i++)
                #pragma unroll
                for (int j = 0; j < 8; j++)
                    mma16816(acc[i][j], a[i], b[j]);
        }
    }

    // ---- epilogue ----
    const int row0 = by * 128 + wm * 64 + (lane >> 2);
    const int col0 = bx * 128 + wn * 64 + (lane & 3) * 2;
    #pragma unroll
    for (int j = 0; j < 8; j++) {
        const int col = col0 + j * 8;
        const float2 bv = *(const float2*)&bias[col];
        #pragma unroll
        for (int i = 0; i < 4; i++) {
            #pragma unroll
            for (int half = 0; half < 2; half++) {
                const int row = row0 + i * 16 + half * 8;
                float v0 = acc[i][j][half * 2 + 0] + bv.x;
                float v1 = acc[i][j][half * 2 + 1] + bv.y;
                if (MODE == 2) {
                    v0 = 0.5f * v0 * (1.0f + erff(v0 * 0.70710678118654752f));
                    v1 = 0.5f * v1 * (1.0f + erff(v1 * 0.70710678118654752f));
                    *(__half2*)(C3 + (size_t)row * N + col) =
                        __halves2half2(__float2half_rn(v0), __float2half_rn(v1));
                } else if (MODE == 3) {
                    *(__half2*)(C3 + (size_t)row * N + col) =
                        __halves2half2(__float2half_rn(v0), __float2half_rn(v1));
                } else {  // MODE 1: qkv split epilogue (all natural layouts)
                    const int sec = col >> 10;
                    const int within = col & 1023;
                    const __half2 hv = __halves2half2(__float2half_rn(v0), __float2half_rn(v1));
                    if (sec == 0)      *(__half2*)(q2p + (size_t)row * 1024 + within) = hv;
                    else if (sec == 1) *(__half2*)(k2p + (size_t)row * 1024 + within) = hv;
                    else               *(__half2*)(v2p + (size_t)row * 1024 + within) = hv;
                }
            }
        }
    }
}

// ===================== FA2 flash attention (Q64, 4 CTAs/SM) ==================
// grid (S/64, H, B) = 1024 CTAs, 128 threads (4 warps, each 16 rows x 64 n).
// Register softmax via h2exp2; fp16 P doubles as PV A-operand.
// V natural [tok][d]; PV B-fragments via ldmatrix.trans. Triple-buffered K/V.
#define SQ2 0                    // 8KB (64 rows x 128B)
#define SKV 8192                 // 3 x (8KB K + 8KB V)
#define AT_SMEM (8192 + 3 * 16384)   // 57344

__global__ __launch_bounds__(128, 4)
void flash_mma_kernel(const __half* __restrict__ q2, const __half* __restrict__ k2,
                      const __half* __restrict__ v2, __half* __restrict__ attn2)
{
    extern __shared__ __align__(1024) char sm_[];
    const uint32_t sb = smem_to_u32(sm_);

    const int tid = threadIdx.x, lane = tid & 31, w = tid >> 5;
    const int qb = blockIdx.x, h = blockIdx.y, b = blockIdx.z;
    const int NKB = Ssz / 64;   // 32

    const char* qsrc = (const char*)q2 + ((size_t)(b * Ssz + qb * 64) * 1024 + h * 64) * 2;
    const char* ksrc = (const char*)k2 + ((size_t)b * Ssz * 1024 + h * 64) * 2;
    const char* vsrc = (const char*)v2 + ((size_t)b * Ssz * 1024 + h * 64) * 2;

    // ---- prologue: Q + (K,V)(0) [group0], (K,V)(1) [group1] ----
    #pragma unroll
    for (int it = 0; it < 4; it++) {
        const int idx = tid + it * 128;
        const int r = idx >> 3;
        const int c = (idx & 7) * 16;
        CPASYNC16(sb + SQ2 + swadr(r, 128, c), qsrc + (size_t)r * 2048 + c);
    }
    #pragma unroll
    for (int p = 0; p < 2; p++) {
        const uint32_t ko = SKV + p * 16384;
        const uint32_t vo = ko + 8192;
        #pragma unroll
        for (int it = 0; it < 4; it++) {
            const int idx = tid + it * 128;
            const int r = idx >> 3;
            const int c = (idx & 7) * 16;
            CPASYNC16(sb + ko + swadr(r, 128, c), ksrc + (size_t)(p * 64 + r) * 2048 + c);
            CPASYNC16(sb + vo + swadr(r, 128, c), vsrc + (size_t)(p * 64 + r) * 2048 + c);
        }
        CPASYNC_COMMIT();
    }

    const int a_row = lane & 15;
    const int a_part = (lane >> 4) * 16;
    const int b_rowo = ((lane >> 4) << 3) + (lane & 7);
    const int b_part = ((lane >> 3) & 1) * 16;
    // trans-ldmatrix lane map (B from token-major V tile)
    const int v_row = lane & 15;
    const int v_col = (lane >> 4) * 16;

    uint32_t q[4][4];
    float o[8][4];
    #pragma unroll
    for (int j = 0; j < 8; j++)
        #pragma unroll
        for (int u = 0; u < 4; u++) o[j][u] = 0.0f;
    float m0 = -INFINITY, m1 = -INFINITY, l0 = 0.0f, l1 = 0.0f;

    #pragma unroll 1
    for (int kb = 0; kb < NKB; kb++) {
        if (kb + 1 < NKB) CPASYNC_WAIT1();
        else              CPASYNC_WAIT0();
        __syncthreads();   // (a) K/V(kb) visible; (b) all warps past kb-1 reads

        // prefetch (kb+2) into buffer (kb+2)%3 — last read at iter kb-1
        if (kb + 2 < NKB) {
            const uint32_t ko = SKV + ((kb + 2) % 3) * 16384;
            const uint32_t vo = ko + 8192;
            #pragma unroll
            for (int it = 0; it < 4; it++) {
                const int idx = tid + it * 128;
                const int r = idx >> 3;
                const int c = (idx & 7) * 16;
                CPASYNC16(sb + ko + swadr(r, 128, c),
                          ksrc + (size_t)((kb + 2) * 64 + r) * 2048 + c);
                CPASYNC16(sb + vo + swadr(r, 128, c),
                          vsrc + (size_t)((kb + 2) * 64 + r) * 2048 + c);
            }
            CPASYNC_COMMIT();
        }

        if (kb == 0) {
            // load Q fragments once; pre-scale by 1/8 (exact in fp16)
            const __half2 sc = __half2half2(__float2half(0.125f));
            #pragma unroll
            for (int ks = 0; ks < 4; ks++) {
                ldmatrix_x4(q[ks][0], q[ks][1], q[ks][2], q[ks][3],
                            sb + SQ2 + swadr((uint32_t)(16 * w + a_row), 128,
                                             (uint32_t)(ks * 32 + a_part)));
                #pragma unroll
                for (int u = 0; u < 4; u++) {
                    __half2 t = *(__half2*)&q[ks][u];
                    t = __hmul2(t, sc);
                    q[ks][u] = *(uint32_t*)&t;
                }
            }
        }

        const uint32_t kbuf = sb + SKV + (kb % 3) * 16384;
        const uint32_t vbuf = kbuf + 8192;

        // ---- S = Q K^T : warp tile 16(m) x 64(n tokens), 4 k-steps ----
        float s[8][4];
        #pragma unroll
        for (int j = 0; j < 8; j++)
            #pragma unroll
            for (int u = 0; u < 4; u++) s[j][u] = 0.0f;

        #pragma unroll
        for (int ks = 0; ks < 4; ks++) {
            #pragma unroll
            for (int jb = 0; jb < 4; jb++) {
                uint32_t r0, r1, r2, r3;
                ldmatrix_x4(r0, r1, r2, r3,
                            kbuf + swadr((uint32_t)(jb * 16 + b_rowo), 128,
                                         (uint32_t)(ks * 32 + b_part)));
                uint32_t bfr0[2] = {r0, r1}, bfr1[2] = {r2, r3};
                mma16816(s[2 * jb], q[ks], bfr0);
                mma16816(s[2 * jb + 1], q[ks], bfr1);
            }
        }

        // ---- register online softmax (rows r0 = lane>>2, r1 = r0+8) ----
        float vmax0 = -INFINITY, vmax1 = -INFINITY;
        #pragma unroll
        for (int j = 0; j < 8; j++) {
            vmax0 = fmaxf(vmax0, fmaxf(s[j][0], s[j][1]));
            vmax1 = fmaxf(vmax1, fmaxf(s[j][2], s[j][3]));
        }
        vmax0 = fmaxf(vmax0, __shfl_xor_sync(0xffffffffu, vmax0, 1));
        vmax0 = fmaxf(vmax0, __shfl_xor_sync(0xffffffffu, vmax0, 2));
        vmax1 = fmaxf(vmax1, __shfl_xor_sync(0xffffffffu, vmax1, 1));
        vmax1 = fmaxf(vmax1, __shfl_xor_sync(0xffffffffu, vmax1, 2));

        const float mn0 = fmaxf(m0, vmax0);
        const float mn1 = fmaxf(m1, vmax1);
        const float c0 = __expf(m0 - mn0);
        const float c1 = __expf(m1 - mn1);
        m0 = mn0; m1 = mn1;

        // P = exp2((s-m)*log2e) via h2exp2, stored as packed fp16 pairs
        const float L2E = 1.44269504088896f;
        uint32_t plo[8], phi[8];
        float rs0 = 0.0f, rs1 = 0.0f;
        #pragma unroll
        for (int j = 0; j < 8; j++) {
            __half2 t0 = __floats2half2_rn((s[j][0] - mn0) * L2E, (s[j][1] - mn0) * L2E);
            __half2 t1 = __floats2half2_rn((s[j][2] - mn1) * L2E, (s[j][3] - mn1) * L2E);
            const __half2 p0 = h2exp2(t0);
            const __half2 p1 = h2exp2(t1);
            plo[j] = *(uint32_t*)&p0;
            phi[j] = *(uint32_t*)&p1;
            const float2 f0 = __half22float2(p0);
            const float2 f1 = __half22float2(p1);
            rs0 += f0.x + f0.y;
            rs1 += f1.x + f1.y;
        }
        rs0 += __shfl_xor_sync(0xffffffffu, rs0, 1);
        rs0 += __shfl_xor_sync(0xffffffffu, rs0, 2);
        rs1 += __shfl_xor_sync(0xffffffffu, rs1, 1);
        rs1 += __shfl_xor_sync(0xffffffffu, rs1, 2);
        l0 = l0 * c0 + rs0;
        l1 = l1 * c1 + rs1;
        #pragma unroll
        for (int j = 0; j < 8; j++) {
            o[j][0] *= c0; o[j][1] *= c0;
            o[j][2] *= c1; o[j][3] *= c1;
        }

        // ---- O += P V : B-fragments from token-major V via ldmatrix.trans ----
        #pragma unroll
        for (int ks = 0; ks < 4; ks++) {
            uint32_t a[4];
            a[0] = plo[2 * ks];
            a[1] = phi[2 * ks];
            a[2] = plo[2 * ks + 1];
            a[3] = phi[2 * ks + 1];
            #pragma unroll
            for (int jb = 0; jb < 4; jb++) {
                uint32_t r0, r1, r2, r3;
                ldmatrix_x4_trans(r0, r1, r2, r3,
                                  vbuf + swadr((uint32_t)(ks * 16 + v_row), 128,
                                               (uint32_t)(jb * 32 + v_col)));
                uint32_t bfr0[2] = {r0, r1}, bfr1[2] = {r2, r3};
                mma16816(o[2 * jb], a, bfr0);
                mma16816(o[2 * jb + 1], a, bfr1);
            }
        }
    }

    // ---- epilogue ----
    const float inv0 = 1.0f / l0;
    const float inv1 = 1.0f / l1;
    const size_t r0g = (size_t)b * Ssz + (size_t)qb * 64 + 16 * w + (lane >> 2);
    const size_t r1g = r0g + 8;
    #pragma unroll
    for (int j = 0; j < 8; j++) {
        const int col = h * 64 + j * 8 + (lane & 3) * 2;
        *(__half2*)(attn2 + r0g * 1024 + col) = __halves2half2(
            __float2half_rn(o[j][0] * inv0), __float2half_rn(o[j][1] * inv0));
        *(__half2*)(attn2 + r1g * 1024 + col) = __halves2half2(
            __float2half_rn(o[j][2] * inv1), __float2half_rn(o[j][3] * inv1));
    }
}

// ===================== fused residual-add + LayerNorm ========================
// MODE 0: A fp32 + B fp16 -> Y2 fp16 only (LN1).
// MODE 1: A fp16 + B fp16 -> Y fp32 only (LN2 / final output).
template<int MODE>
__global__ __launch_bounds__(256)
void add_ln_kernel(const float* __restrict__ Af, const __half* __restrict__ Ah,
                   const __half* __restrict__ Bv,
                   const float* __restrict__ g, const float* __restrict__ be,
                   float* __restrict__ Y, __half* __restrict__ Y2)
{
    const int row = blockIdx.x;
    const int tid = threadIdx.x;
    float a0, a1, a2, a3;
    if (MODE == 0) {
        const float4 av = ((const float4*)(Af + (size_t)row * Esz))[tid];
        a0 = av.x; a1 = av.y; a2 = av.z; a3 = av.w;
    } else {
        const __half2 ah0 = ((const __half2*)(Ah + (size_t)row * Esz))[tid * 2];
        const __half2 ah1 = ((const __half2*)(Ah + (size_t)row * Esz))[tid * 2 + 1];
        const float2 af0 = __half22float2(ah0);
        const float2 af1 = __half22float2(ah1);
        a0 = af0.x; a1 = af0.y; a2 = af1.x; a3 = af1.y;
    }
    const __half2 b0 = ((const __half2*)(Bv + (size_t)row * Esz))[tid * 2];
    const __half2 b1 = ((const __half2*)(Bv + (size_t)row * Esz))[tid * 2 + 1];
    const float2 bf0 = __half22float2(b0);
    const float2 bf1 = __half22float2(b1);
    const float v0 = a0 + bf0.x, v1 = a1 + bf0.y, v2 = a2 + bf1.x, v3 = a3 + bf1.y;

    float s = v0 + v1 + v2 + v3;
    float s2 = v0 * v0 + v1 * v1 + v2 * v2 + v3 * v3;
    #pragma unroll
    for (int o = 16; o; o >>= 1) {
        s += __shfl_xor_sync(0xffffffffu, s, o);
        s2 += __shfl_xor_sync(0xffffffffu, s2, o);
    }
    __shared__ float ss[8], ss2[8];
    const int w = tid >> 5, ln = tid & 31;
    if (ln == 0) { ss[w] = s; ss2[w] = s2; }
    __syncthreads();
    if (tid < 8) {
        s = ss[tid]; s2 = ss2[tid];
        #pragma unroll
        for (int o = 4; o; o >>= 1) {
            s += __shfl_xor_sync(0x000000ffu, s, o);
            s2 += __shfl_xor_sync(0x000000ffu, s2, o);
        }
        if (tid == 0) { ss[0] = s; ss2[0] = s2; }
    }
    __syncthreads();
    const float mean = ss[0] * (1.0f / Esz);
    const float var = ss2[0] * (1.0f / Esz) - mean * mean;
    const float rstd = rsqrtf(var + 1e-5f);

    const float4 gv = ((const float4*)g)[tid];
    const float4 bev = ((const float4*)be)[tid];
    float o4x = (v0 - mean) * rstd * gv.x + bev.x;
    float o4y = (v1 - mean) * rstd * gv.y + bev.y;
    float o4z = (v2 - mean) * rstd * gv.z + bev.z;
    float o4w = (v3 - mean) * rstd * gv.w + bev.w;

    if (MODE == 0) {
        __half* base = Y2 + (size_t)row * 1024 + tid * 4;
        *(__half2*)(base) = __halves2half2(__float2half_rn(o4x), __float2half_rn(o4y));
        *(__half2*)(base + 2) = __halves2half2(__float2half_rn(o4z), __float2half_rn(o4w));
    } else {
        ((float4*)(Y + (size_t)row * Esz))[tid] = make_float4(o4x, o4y, o4z, o4w);
    }
}

// ===================== launch ================================================
extern "C" void kernel_launch(void* const* d_in, const int* in_sizes, int n_in,
                              void* d_out, int out_size)
{
    (void)in_sizes; (void)n_in; (void)out_size;
    const float* x     = (const float*)d_in[0];
    const float* w_qkv = (const float*)d_in[1];
    const float* b_qkv = (const float*)d_in[2];
    const float* w_out = (const float*)d_in[3];
    const float* b_out = (const float*)d_in[4];
    const float* g1    = (const float*)d_in[5];
    const float* beta1 = (const float*)d_in[6];
    const float* w_fc1 = (const float*)d_in[7];
    const float* b_fc1 = (const float*)d_in[8];
    const float* w_fc2 = (const float*)d_in[9];
    const float* b_fc2 = (const float*)d_in[10];
    const float* g2    = (const float*)d_in[11];
    const float* beta2 = (const float*)d_in[12];

    __half *proj16, *ff16, *q2, *k2, *v2, *attn2, *x2, *x12, *h2, *wq2, *wo2, *w12, *w22;
    cudaGetSymbolAddress((void**)&proj16, g_proj16);
    cudaGetSymbolAddress((void**)&ff16,   g_ff16);
    cudaGetSymbolAddress((void**)&q2,     g_q2);
    cudaGetSymbolAddress((void**)&k2,     g_k2);
    cudaGetSymbolAddress((void**)&v2,     g_v2);
    cudaGetSymbolAddress((void**)&attn2,  g_attn2);
    cudaGetSymbolAddress((void**)&x2,     g_x2);
    cudaGetSymbolAddress((void**)&x12,    g_x12);
    cudaGetSymbolAddress((void**)&h2,     g_h2);
    cudaGetSymbolAddress((void**)&wq2,    g_wqkv2);
    cudaGetSymbolAddress((void**)&wo2,    g_wout2);
    cudaGetSymbolAddress((void**)&w12,    g_wfc12);
    cudaGetSymbolAddress((void**)&w22,    g_wfc22);

    cudaFuncSetAttribute(flash_mma_kernel, cudaFuncAttributeMaxDynamicSharedMemorySize, AT_SMEM);
    cudaFuncSetAttribute(gemm_mma_kernel<1>, cudaFuncAttributeMaxDynamicSharedMemorySize, GEMM_SMEM);
    cudaFuncSetAttribute(gemm_mma_kernel<2>, cudaFuncAttributeMaxDynamicSharedMemorySize, GEMM_SMEM);
    cudaFuncSetAttribute(gemm_mma_kernel<3>, cudaFuncAttributeMaxDynamicSharedMemorySize, GEMM_SMEM);

    // 0) all fp32->fp16 converts in one kernel (16B vectorized stores)
    cvt_all_kernel<<<2048, 256>>>(w_qkv, w_out, w_fc1, w_fc2, x, wq2, wo2, w12, w22, x2);

    // 1) qkv = x @ w_qkv^T + b_qkv  -> q2/k2/v2 (all natural fp16)
    gemm_mma_kernel<1><<<dim3(3 * Esz / 128, Msz / 128), 128, GEMM_SMEM>>>(
        x2, wq2, b_qkv, nullptr, q2, k2, v2, 3 * Esz, Esz, Esz, Esz);
    // 2) attention -> attn2  (Q64 tiles, 4 CTAs/SM)
    flash_mma_kernel<<<dim3(Ssz / 64, Hsz, Bsz), 128, AT_SMEM>>>(q2, k2, v2, attn2);
    // 3) proj16 = fp16(attn @ w_out^T + b_out)
    gemm_mma_kernel<3><<<dim3(Esz / 128, Msz / 128), 128, GEMM_SMEM>>>(
        attn2, wo2, b_out, proj16, nullptr, nullptr, nullptr, Esz, Esz, Esz, Esz);
    // 4) x12 = fp16(LN(x + proj16))
    add_ln_kernel<0><<<Msz, 256>>>(x, nullptr, proj16, g1, beta1, nullptr, x12);
    // 5) h2 = fp16(gelu(x12 @ w_fc1^T + b_fc1))
    gemm_mma_kernel<2><<<dim3(FFsz / 128, Msz / 128), 128, GEMM_SMEM>>>(
        x12, w12, b_fc1, h2, nullptr, nullptr, nullptr, FFsz, Esz, Esz, Esz);
    // 6) ff16 = fp16(h @ w_fc2^T + b_fc2)
    gemm_mma_kernel<3><<<dim3(Esz / 128, Msz / 128), 128, GEMM_SMEM>>>(
        h2, w22, b_fc2, ff16, nullptr, nullptr, nullptr, Esz, FFsz, FFsz, FFsz);
    // 7) out = LN(x12 + ff16)   (fp32 output)
    add_ln_kernel<1><<<Msz, 256>>>(nullptr, x12, ff16, g2, beta2, (float*)d_out, nullptr);
}